// round 16
// baseline (speedup 1.0000x reference)
#include <cuda_runtime.h>
#include <cuda_fp16.h>
#include <cstdint>
#include <math.h>

#define BATCH  16384
#define DMODEL 2048
#define RANK   64
#define NPROJ  192

// fp16 weight mirrors (static scratch; no allocation)
__device__ __half d_Wh[NPROJ * DMODEL];      // concat [Wdt;Wph;WB], 768 KB
__device__ __half d_WCh[DMODEL * RANK];      // 256 KB

// ---------------------------------------------------------------------------
// helpers
// ---------------------------------------------------------------------------
__device__ __forceinline__ uint32_t smem_u32(const void* p) {
    uint32_t a;
    asm("{ .reg .u64 t; cvta.to.shared.u64 t, %1; cvt.u32.u64 %0, t; }"
        : "=r"(a) : "l"(p));
    return a;
}
__device__ __forceinline__ void mma_f16(float* d, const uint32_t* A, const uint32_t* B) {
    asm volatile(
        "mma.sync.aligned.m16n8k16.row.col.f32.f16.f16.f32 "
        "{%0,%1,%2,%3}, {%4,%5,%6,%7}, {%8,%9}, {%0,%1,%2,%3};\n"
        : "+f"(d[0]), "+f"(d[1]), "+f"(d[2]), "+f"(d[3])
        : "r"(A[0]), "r"(A[1]), "r"(A[2]), "r"(A[3]), "r"(B[0]), "r"(B[1]));
}
__device__ __forceinline__ void ldsm_x4(uint32_t* r, uint32_t addr) {
    asm volatile("ldmatrix.sync.aligned.m8n8.x4.shared.b16 {%0,%1,%2,%3}, [%4];"
                 : "=r"(r[0]), "=r"(r[1]), "=r"(r[2]), "=r"(r[3]) : "r"(addr));
}
__device__ __forceinline__ void ldsm_x2(uint32_t* r, uint32_t addr) {
    asm volatile("ldmatrix.sync.aligned.m8n8.x2.shared.b16 {%0,%1}, [%2];"
                 : "=r"(r[0]), "=r"(r[1]) : "r"(addr));
}
__device__ __forceinline__ uint2 pack_h4(float4 v) {
    __half2 h0 = __floats2half2_rn(v.x, v.y);
    __half2 h1 = __floats2half2_rn(v.z, v.w);
    uint2 u;
    u.x = *reinterpret_cast<uint32_t*>(&h0);
    u.y = *reinterpret_cast<uint32_t*>(&h1);
    return u;
}
__device__ __forceinline__ void cp16(uint32_t saddr, const void* g) {
    asm volatile("cp.async.cg.shared.global [%0], [%1], 16;" :: "r"(saddr), "l"(g));
}
#define CP_COMMIT() asm volatile("cp.async.commit_group;" ::: "memory")
#define CP_WAIT1()  asm volatile("cp.async.wait_group 1;"  ::: "memory")
#define CP_WAIT0()  asm volatile("cp.async.wait_group 0;"  ::: "memory")

// ---------------------------------------------------------------------------
// Kernel 0: f32 -> f16 weight conversion
// ---------------------------------------------------------------------------
__global__ void __launch_bounds__(256) convert_weights(
    const float* __restrict__ Wdt, const float* __restrict__ Wph,
    const float* __restrict__ WB,  const float* __restrict__ WC)
{
    int t = blockIdx.x * 256 + threadIdx.x;
    if (t < NPROJ * DMODEL / 4) {
        int row = t >> 9;
        int c4  = (t & 511) << 2;
        const float* src = (row < 64)  ? (Wdt + (size_t)row * DMODEL)
                         : (row < 128) ? (Wph + (size_t)(row - 64) * DMODEL)
                                       : (WB  + (size_t)(row - 128) * DMODEL);
        float4 v = *reinterpret_cast<const float4*>(src + c4);
        *reinterpret_cast<uint2*>(d_Wh + (size_t)row * DMODEL + c4) = pack_h4(v);
    } else {
        int t2 = t - NPROJ * DMODEL / 4;
        if (t2 < DMODEL * RANK / 4) {
            float4 v = *reinterpret_cast<const float4*>(WC + (size_t)t2 * 4);
            *reinterpret_cast<uint2*>(d_WCh + (size_t)t2 * 4) = pack_h4(v);
        }
    }
}

// ---------------------------------------------------------------------------
// Fused kernel: M-tile 128, BK=128, 512 threads (16 warps, 4x4 warp grid)
// ---------------------------------------------------------------------------
#define LDKH  136                      // halves per row (272 B, conflict-free)
#define ABUFB 34816                    // 128*136*2
#define A0OFF 0
#define A1OFF 34816
#define B0OFF 69632
#define BBUFB 52224                    // 192*136*2
#define NKT   16                       // 2048 / 128
#define LDP   194
// overlays (after phase A the A/B buffers are dead)
#define APOFF  99328                   // after P (128*194*4)
#define LDOH   72
#define WCOFF  117760                  // APOFF + 128*72*2
#define OB_BUF 18432                   // 128*72*2
#define SMEM1  226304                  // A bufs + B bufs

__global__ void __launch_bounds__(512, 1) fused_kernel(
    const float* __restrict__ x,
    const float* __restrict__ sre, const float* __restrict__ sim_,
    const float* __restrict__ bdt, const float* __restrict__ bph,
    const float* __restrict__ Areal, const float* __restrict__ Aimag,
    float* __restrict__ out,
    float* __restrict__ nre, float* __restrict__ nim)
{
    extern __shared__ float smemf[];
    __half* smh = reinterpret_cast<__half*>(smemf);
    const uint32_t sbase = smem_u32(smemf);

    const int tid  = threadIdx.x;
    const int wid  = tid >> 5;
    const int lane = tid & 31;
    const int wm   = wid >> 2;     // 0..3  (32 rows each)
    const int wn   = wid & 3;      // 0..3  (48 cols each)
    const int m0   = blockIdx.x * 128;

    // ================= phase A: projection GEMM (128x192, BK=128) ============
    const int part = lane >> 3, rA = lane & 7;
    uint32_t aLm[2];
    #pragma unroll
    for (int mt = 0; mt < 2; mt++) {
        int row  = wm * 32 + mt * 16 + (part & 1) * 8 + rA;
        int colh = (part >> 1) * 8;
        aLm[mt] = sbase + A0OFF + (uint32_t)(row * LDKH + colh) * 2;
    }
    const int l16 = lane & 15;
    uint32_t bLm[6];
    #pragma unroll
    for (int nt = 0; nt < 6; nt++) {
        int row  = wn * 48 + nt * 8 + (l16 & 7);
        int colh = (l16 >> 3) * 8;
        bLm[nt] = sbase + B0OFF + (uint32_t)(row * LDKH + colh) * 2;
    }

    // A (x, f32): per half-K (64 floats): 128 rows x 16 float4 = 2048 -> 4/thr
    const float* aP[4]; int aOfs[4];
    #pragma unroll
    for (int i = 0; i < 4; i++) {
        int idx = tid + i * 512;
        int row = idx >> 4, c4 = (idx & 15) << 2;
        aP[i]   = x + (size_t)(m0 + row) * DMODEL + c4;
        aOfs[i] = row * LDKH + c4;
    }
    // B (Wh fp16): 192 rows x 16 chunks(16B) = 3072 -> 6/thread
    const __half* bG[6]; uint32_t bSts[6];
    #pragma unroll
    for (int i = 0; i < 6; i++) {
        int c   = tid + i * 512;
        int row = c >> 4, ch = c & 15;
        bG[i]   = d_Wh + (size_t)row * DMODEL + ch * 8;
        bSts[i] = sbase + B0OFF + (uint32_t)(row * LDKH + ch * 8) * 2;
    }

    float acc[2][6][4];
    #pragma unroll
    for (int i = 0; i < 2; i++)
        #pragma unroll
        for (int j = 0; j < 6; j++)
            #pragma unroll
            for (int k = 0; k < 4; k++) acc[i][j][k] = 0.f;

    float4 ra[4];
    auto ldgAh = [&](int kt, int h) {
        #pragma unroll
        for (int i = 0; i < 4; i++)
            ra[i] = *reinterpret_cast<const float4*>(aP[i] + kt * 128 + h * 64);
    };
    auto stsAh = [&](int ab, int h) {
        __half* dst = smh + (ab ? A1OFF / 2 : 0) + h * 64;
        #pragma unroll
        for (int i = 0; i < 4; i++)
            *reinterpret_cast<uint2*>(dst + aOfs[i]) = pack_h4(ra[i]);
    };
    auto cpB = [&](int kt, int b3) {
        const uint32_t so = (uint32_t)b3 * BBUFB;
        #pragma unroll
        for (int i = 0; i < 6; i++)
            cp16(bSts[i] + so, bG[i] + kt * 128);
        CP_COMMIT();
    };
    auto compute4 = [&](uint32_t aOffB, uint32_t bOffB, int k16lo) {
        #pragma unroll
        for (int s = 0; s < 4; s++) {
            const uint32_t kB = (uint32_t)(k16lo + s) * 32;
            uint32_t afr[2][4], bfr[6][2];
            #pragma unroll
            for (int mt = 0; mt < 2; mt++) ldsm_x4(afr[mt], aLm[mt] + aOffB + kB);
            #pragma unroll
            for (int nt = 0; nt < 6; nt++) ldsm_x2(bfr[nt], bLm[nt] + bOffB + kB);
            #pragma unroll
            for (int mt = 0; mt < 2; mt++)
                #pragma unroll
                for (int nt = 0; nt < 6; nt++)
                    mma_f16(acc[mt][nt], afr[mt], bfr[nt]);
        }
    };

    // prologue: B(0), B(1) via cp.async; A(0) staged synchronously
    cpB(0, 0);
    cpB(1, 1);
    ldgAh(0, 0); stsAh(0, 0);
    ldgAh(0, 1); stsAh(0, 1);
    CP_WAIT1();                // B(0) arrived
    __syncthreads();

    int cur3 = 0;
    for (int kt = 0; kt < NKT; ++kt) {
        const int ab = kt & 1;
        const uint32_t aOffB = ab ? (uint32_t)A1OFF : 0u;
        const uint32_t bOffB = (uint32_t)cur3 * BBUFB;

        if (kt + 1 < NKT) ldgAh(kt + 1, 0);          // LDG h0 under compute
        compute4(aOffB, bOffB, 0);
        if (kt + 1 < NKT) {
            stsAh(ab ^ 1, 0);
            ldgAh(kt + 1, 1);                        // LDG h1 under compute
        }
        compute4(aOffB, bOffB, 4);
        if (kt + 1 < NKT) {
            stsAh(ab ^ 1, 1);
            if (kt + 2 < NKT) {
                int nxt = cur3 + 2; if (nxt >= 3) nxt -= 3;
                cpB(kt + 2, nxt);
                CP_WAIT1();                          // B(kt+1) arrived
            } else {
                CP_WAIT0();
            }
            __syncthreads();
        }
        cur3 = (cur3 + 1 == 3) ? 0 : cur3 + 1;
    }
    __syncthreads();

    // ================= stage P (128 x 192, f32) =================
    const int g = lane >> 2, t = lane & 3;
    float* P = smemf;
    #pragma unroll
    for (int mt = 0; mt < 2; mt++) {
        int r0 = wm * 32 + mt * 16 + g;
        #pragma unroll
        for (int nt = 0; nt < 6; nt++) {
            int c0 = wn * 48 + nt * 8 + 2 * t;
            *reinterpret_cast<float2*>(P + r0 * LDP + c0) =
                make_float2(acc[mt][nt][0], acc[mt][nt][1]);
            *reinterpret_cast<float2*>(P + (r0 + 8) * LDP + c0) =
                make_float2(acc[mt][nt][2], acc[mt][nt][3]);
        }
    }
    __syncthreads();

    // ================= phase B: elementwise state update =================
    {
        const float PI_F = 3.14159265358979323846f;
        const int r = tid & 63;
        const float bdt_r = bdt[r];
        const float bph_r = bph[r];
        const float eA_r  = __expf(Areal[r]);
        const float Ai_r  = Aimag[r];
        __half* Ap = smh + APOFF / 2;          // A' fp16 128 x LDOH

        #pragma unroll
        for (int i = 0; i < 16; i++) {
            int idx  = tid + i * 512;          // 8192 = 128*64
            int row  = idx >> 6;
            int grow = m0 + row;

            float zdt   = P[row * LDP + r] + bdt_r;
            float dt    = (zdt > 15.f) ? zdt : __logf(1.f + __expf(zdt));
            float zph   = P[row * LDP + 64 + r] + bph_r;
            float e2z   = __expf(2.f * zph);
            float th    = 1.f - __fdividef(2.f, 1.f + e2z);
            float phase = th * PI_F;
            float decay = __expf(-dt * eA_r);
            float angle = fmaf(dt, Ai_r, phase);
            float Bv    = P[row * LDP + 128 + r];

            float sn = __sinf(angle);
            float cs = __cosf(angle);

            float a_ = sre[(size_t)grow * RANK + r];
            float b_ = sim_[(size_t)grow * RANK + r];

            float vre = fmaf(a_ * cs - b_ * sn, decay, Bv);
            nre[(size_t)grow * RANK + r] = vre;
            nim[(size_t)grow * RANK + r] = (a_ * sn + b_ * cs) * decay;
            Ap[row * LDOH + r] = __float2half(vre);
        }
    }
    __syncthreads();

    // ================= phase C: out = A' @ WC^T  (128 x 2048) =================
    uint32_t aLm2[2];
    #pragma unroll
    for (int mt = 0; mt < 2; mt++) {
        int row  = wm * 32 + mt * 16 + (part & 1) * 8 + rA;
        int colh = (part >> 1) * 8;
        aLm2[mt] = sbase + APOFF + (uint32_t)(row * LDOH + colh) * 2;
    }
    uint32_t bLm2[4];
    #pragma unroll
    for (int nt = 0; nt < 4; nt++) {
        int row  = wn * 32 + nt * 8 + (l16 & 7);
        int colh = (l16 >> 3) * 8;
        bLm2[nt] = sbase + WCOFF + (uint32_t)(row * LDOH + colh) * 2;
    }

    auto cpWC = [&](int t128, int b3) {
        const uint32_t so = (uint32_t)WCOFF + (uint32_t)b3 * OB_BUF;
        #pragma unroll
        for (int i = 0; i < 2; i++) {
            int c = tid + i * 512;             // 1024 x 16B chunks
            int row = c >> 3, ch = c & 7;
            cp16(sbase + so + (uint32_t)(row * LDOH + ch * 8) * 2,
                 d_WCh + ((size_t)t128 * 128 + row) * RANK + ch * 8);
        }
        CP_COMMIT();
    };

    cpWC(0, 0);
    cpWC(1, 1);
    CP_WAIT1();
    __syncthreads();

    int c3 = 0;
    for (int t128 = 0; t128 < 16; ++t128) {
        float acc2[2][4][4];
        #pragma unroll
        for (int i = 0; i < 2; i++)
            #pragma unroll
            for (int j = 0; j < 4; j++)
                #pragma unroll
                for (int k = 0; k < 4; k++) acc2[i][j][k] = 0.f;

        const uint32_t so = (uint32_t)c3 * OB_BUF;
        #pragma unroll
        for (int k16 = 0; k16 < 4; k16++) {
            const uint32_t kB = (uint32_t)k16 * 32;
            uint32_t afr[2][4], bfr[4][2];
            #pragma unroll
            for (int mt = 0; mt < 2; mt++) ldsm_x4(afr[mt], aLm2[mt] + kB);
            #pragma unroll
            for (int nt = 0; nt < 4; nt++) ldsm_x2(bfr[nt], bLm2[nt] + so + kB);
            #pragma unroll
            for (int mt = 0; mt < 2; mt++)
                #pragma unroll
                for (int nt = 0; nt < 4; nt++)
                    mma_f16(acc2[mt][nt], afr[mt], bfr[nt]);
        }

        const int n0 = t128 * 128;
        #pragma unroll
        for (int mt = 0; mt < 2; mt++) {
            int row = m0 + wm * 32 + mt * 16 + g;
            #pragma unroll
            for (int nt = 0; nt < 4; nt++) {
                int col = n0 + wn * 32 + nt * 8 + 2 * t;
                *reinterpret_cast<float2*>(out + (size_t)row * DMODEL + col) =
                    make_float2(acc2[mt][nt][0], acc2[mt][nt][1]);
                *reinterpret_cast<float2*>(out + (size_t)(row + 8) * DMODEL + col) =
                    make_float2(acc2[mt][nt][2], acc2[mt][nt][3]);
            }
        }

        if (t128 + 2 < 16) {
            int nxt = c3 + 2; if (nxt >= 3) nxt -= 3;
            cpWC(t128 + 2, nxt);
            CP_WAIT1();
            __syncthreads();
        } else if (t128 + 1 < 16) {
            CP_WAIT0();
            __syncthreads();
        }
        c3 = (c3 + 1 == 3) ? 0 : c3 + 1;
    }
}

// ---------------------------------------------------------------------------
// launch
// ---------------------------------------------------------------------------
extern "C" void kernel_launch(void* const* d_in, const int* in_sizes, int n_in,
                              void* d_out, int out_size)
{
    const float* x    = (const float*)d_in[0];
    const float* sre  = (const float*)d_in[1];
    const float* sim_ = (const float*)d_in[2];
    const float* Wdt  = (const float*)d_in[3];
    const float* bdt  = (const float*)d_in[4];
    const float* Wph  = (const float*)d_in[5];
    const float* bph  = (const float*)d_in[6];
    const float* WB   = (const float*)d_in[7];
    const float* WC   = (const float*)d_in[8];
    const float* Ar   = (const float*)d_in[9];
    const float* Ai   = (const float*)d_in[10];

    float* out = (float*)d_out;
    float* nre = out + (size_t)BATCH * DMODEL;
    float* nim = nre + (size_t)BATCH * RANK;

    cudaFuncSetAttribute(fused_kernel, cudaFuncAttributeMaxDynamicSharedMemorySize, SMEM1);

    convert_weights<<<512, 256>>>(Wdt, Wph, WB, WC);
    fused_kernel<<<BATCH / 128, 512, SMEM1>>>(x, sre, sim_, bdt, bph, Ar, Ai,
                                              out, nre, nim);
}

// round 17
// speedup vs baseline: 1.1103x; 1.1103x over previous
#include <cuda_runtime.h>
#include <cuda_fp16.h>
#include <cstdint>
#include <math.h>

#define BATCH  16384
#define DMODEL 2048
#define RANK   64
#define NPROJ  192

// fp16 weight mirrors (static scratch; no allocation)
__device__ __half d_Wh[NPROJ * DMODEL];      // concat [Wdt;Wph;WB], 768 KB
__device__ __half d_WCh[DMODEL * RANK];      // 256 KB

// ---------------------------------------------------------------------------
// helpers
// ---------------------------------------------------------------------------
__device__ __forceinline__ uint32_t smem_u32(const void* p) {
    uint32_t a;
    asm("{ .reg .u64 t; cvta.to.shared.u64 t, %1; cvt.u32.u64 %0, t; }"
        : "=r"(a) : "l"(p));
    return a;
}
__device__ __forceinline__ void mma_f16(float* d, const uint32_t* A, const uint32_t* B) {
    asm volatile(
        "mma.sync.aligned.m16n8k16.row.col.f32.f16.f16.f32 "
        "{%0,%1,%2,%3}, {%4,%5,%6,%7}, {%8,%9}, {%0,%1,%2,%3};\n"
        : "+f"(d[0]), "+f"(d[1]), "+f"(d[2]), "+f"(d[3])
        : "r"(A[0]), "r"(A[1]), "r"(A[2]), "r"(A[3]), "r"(B[0]), "r"(B[1]));
}
__device__ __forceinline__ void ldsm_x4(uint32_t* r, uint32_t addr) {
    asm volatile("ldmatrix.sync.aligned.m8n8.x4.shared.b16 {%0,%1,%2,%3}, [%4];"
                 : "=r"(r[0]), "=r"(r[1]), "=r"(r[2]), "=r"(r[3]) : "r"(addr));
}
__device__ __forceinline__ uint2 pack_h4(float4 v) {
    __half2 h0 = __floats2half2_rn(v.x, v.y);
    __half2 h1 = __floats2half2_rn(v.z, v.w);
    uint2 u;
    u.x = *reinterpret_cast<uint32_t*>(&h0);
    u.y = *reinterpret_cast<uint32_t*>(&h1);
    return u;
}
__device__ __forceinline__ void cp16(uint32_t saddr, const void* g) {
    asm volatile("cp.async.cg.shared.global [%0], [%1], 16;" :: "r"(saddr), "l"(g));
}
#define CP_COMMIT() asm volatile("cp.async.commit_group;" ::: "memory")
#define CP_WAIT1()  asm volatile("cp.async.wait_group 1;"  ::: "memory")
#define CP_WAIT0()  asm volatile("cp.async.wait_group 0;"  ::: "memory")

// ---------------------------------------------------------------------------
// Kernel 0: f32 -> f16 weight conversion (one float4 per thread)
// ---------------------------------------------------------------------------
__global__ void __launch_bounds__(256) convert_weights(
    const float* __restrict__ Wdt, const float* __restrict__ Wph,
    const float* __restrict__ WB,  const float* __restrict__ WC)
{
    int t = blockIdx.x * 256 + threadIdx.x;
    if (t < NPROJ * DMODEL / 4) {              // 98304 float4 -> Wh
        int row = t >> 9;
        int c4  = (t & 511) << 2;
        const float* src = (row < 64)  ? (Wdt + (size_t)row * DMODEL)
                         : (row < 128) ? (Wph + (size_t)(row - 64) * DMODEL)
                                       : (WB  + (size_t)(row - 128) * DMODEL);
        float4 v = *reinterpret_cast<const float4*>(src + c4);
        *reinterpret_cast<uint2*>(d_Wh + (size_t)row * DMODEL + c4) = pack_h4(v);
    } else {
        int t2 = t - NPROJ * DMODEL / 4;       // 32768 float4 -> WCh
        if (t2 < DMODEL * RANK / 4) {
            float4 v = *reinterpret_cast<const float4*>(WC + (size_t)t2 * 4);
            *reinterpret_cast<uint2*>(d_WCh + (size_t)t2 * 4) = pack_h4(v);
        }
    }
}

// ---------------------------------------------------------------------------
// Fused kernel (R15 geometry): proj GEMM (64x192, BK=64) + update + out GEMM
// B fragments via paired ldmatrix.x4 (n16 per load).
// ---------------------------------------------------------------------------
#define LDKH  72                       // halves per smem row (144 B, conflict-free)
#define A0OFF 0
#define A1OFF 9216                     // 64*72*2
#define B0OFF 18432
#define BBUFB 27648                    // 192*72*2
#define LDP   194
#define NKT   (DMODEL / 64)            // 32 K-tiles
// phase C
#define LDOH   72
#define OB_BUF 18432                   // 128*72*2, buffers live at B0OFF
#define APOFF  101376                  // after B buffers (18432 + 3*27648)
#define SMEM1  110592                  // APOFF + 64*72*2

__global__ void __launch_bounds__(256, 2) fused_kernel(
    const float* __restrict__ x,
    const float* __restrict__ sre, const float* __restrict__ sim_,
    const float* __restrict__ bdt, const float* __restrict__ bph,
    const float* __restrict__ Areal, const float* __restrict__ Aimag,
    float* __restrict__ out,
    float* __restrict__ nre, float* __restrict__ nim)
{
    extern __shared__ float smemf[];
    __half* smh = reinterpret_cast<__half*>(smemf);
    const uint32_t sbase = smem_u32(smemf);

    const int tid  = threadIdx.x;
    const int wid  = tid >> 5;
    const int lane = tid & 31;
    const int wm   = wid >> 2;     // 0..1
    const int wn   = wid & 3;      // 0..3
    const int m0   = blockIdx.x * 64;

    // ================= phase A: projection GEMM (BK=64) =================
    const int part = lane >> 3, rA = lane & 7;
    uint32_t aLm[2];
    #pragma unroll
    for (int mt = 0; mt < 2; mt++) {
        int row  = wm * 32 + mt * 16 + (part & 1) * 8 + rA;
        int colh = (part >> 1) * 8;
        aLm[mt] = sbase + A0OFF + (uint32_t)(row * LDKH + colh) * 2;
    }
    // B: paired n16 x4 loads. quads 0,1 -> rows nb..nb+7 (cols 0/8);
    //                         quads 2,3 -> rows nb+8..nb+15 (cols 0/8)
    const int hi8  = (lane >> 4) << 3;       // +8 rows for lanes 16..31
    const int col8 = ((lane >> 3) & 1) * 8;  // 8-half col split
    uint32_t bLm[3];
    #pragma unroll
    for (int p = 0; p < 3; p++) {
        int row = wn * 48 + p * 16 + hi8 + rA;
        bLm[p] = sbase + B0OFF + (uint32_t)(row * LDKH + col8) * 2;
    }

    // A (x, f32): 64 rows x 16 float4 = 1024 -> 4/thread
    const float* aP[4]; int aOfs[4];
    #pragma unroll
    for (int i = 0; i < 4; i++) {
        int idx = tid + i * 256;
        int row = idx >> 4, c4 = (idx & 15) << 2;
        aP[i]   = x + (size_t)(m0 + row) * DMODEL + c4;
        aOfs[i] = row * LDKH + c4;
    }
    // B (Wh, fp16): 192 rows x 8 chunks(16B) = 1536 -> 6/thread
    const __half* bG[6]; uint32_t bSts[6];
    #pragma unroll
    for (int i = 0; i < 6; i++) {
        int c   = tid + i * 256;
        int row = c >> 3, ch = c & 7;
        bG[i]   = d_Wh + (size_t)row * DMODEL + ch * 8;
        bSts[i] = sbase + B0OFF + (uint32_t)(row * LDKH + ch * 8) * 2;
    }

    float acc[2][6][4];
    #pragma unroll
    for (int i = 0; i < 2; i++)
        #pragma unroll
        for (int j = 0; j < 6; j++)
            #pragma unroll
            for (int k = 0; k < 4; k++) acc[i][j][k] = 0.f;

    float4 ra[4];
    auto ldgA = [&](int kt) {
        #pragma unroll
        for (int i = 0; i < 4; i++)
            ra[i] = *reinterpret_cast<const float4*>(aP[i] + kt * 64);
    };
    auto stsA = [&](int ab) {
        __half* dst = smh + (ab ? A1OFF / 2 : 0);
        #pragma unroll
        for (int i = 0; i < 4; i++)
            *reinterpret_cast<uint2*>(dst + aOfs[i]) = pack_h4(ra[i]);
    };
    auto cpB = [&](int kt, int b3) {
        const uint32_t so = (uint32_t)b3 * BBUFB;
        #pragma unroll
        for (int i = 0; i < 6; i++)
            cp16(bSts[i] + so, bG[i] + kt * 64);
        CP_COMMIT();
    };

    cpB(0, 0);
    cpB(1, 1);
    ldgA(0); stsA(0);
    ldgA(1);
    CP_WAIT1();
    __syncthreads();

    int cur3 = 0;
    for (int kt = 0; kt < NKT; ++kt) {
        const int ab = kt & 1;
        const uint32_t aOffB = ab ? (uint32_t)A1OFF : 0u;
        const uint32_t bOffB = (uint32_t)cur3 * BBUFB;
        #pragma unroll
        for (int k16 = 0; k16 < 4; k16++) {
            const uint32_t kB = (uint32_t)k16 * 32;
            uint32_t afr[2][4], bfr[3][4];
            #pragma unroll
            for (int mt = 0; mt < 2; mt++) ldsm_x4(afr[mt], aLm[mt] + aOffB + kB);
            #pragma unroll
            for (int p = 0; p < 3; p++)  ldsm_x4(bfr[p], bLm[p] + bOffB + kB);
            #pragma unroll
            for (int mt = 0; mt < 2; mt++)
                #pragma unroll
                for (int nt = 0; nt < 6; nt++)
                    mma_f16(acc[mt][nt], afr[mt], &bfr[nt >> 1][(nt & 1) * 2]);
        }
        if (kt + 1 < NKT) {
            stsA(ab ^ 1);
            if (kt + 2 < NKT) {
                int nxt = cur3 + 2; if (nxt >= 3) nxt -= 3;
                cpB(kt + 2, nxt);
                ldgA(kt + 2);
                CP_WAIT1();
            } else {
                CP_WAIT0();
            }
            __syncthreads();
        }
        cur3 = (cur3 + 1 == 3) ? 0 : cur3 + 1;
    }
    __syncthreads();

    // ================= stage P (64 x 192, f32) =================
    const int g = lane >> 2, t = lane & 3;
    float* P = smemf;
    #pragma unroll
    for (int mt = 0; mt < 2; mt++) {
        int r0 = wm * 32 + mt * 16 + g;
        #pragma unroll
        for (int nt = 0; nt < 6; nt++) {
            int c0 = wn * 48 + nt * 8 + 2 * t;
            *reinterpret_cast<float2*>(P + r0 * LDP + c0) =
                make_float2(acc[mt][nt][0], acc[mt][nt][1]);
            *reinterpret_cast<float2*>(P + (r0 + 8) * LDP + c0) =
                make_float2(acc[mt][nt][2], acc[mt][nt][3]);
        }
    }
    __syncthreads();

    // ================= phase B: elementwise state update =================
    {
        const float PI_F = 3.14159265358979323846f;
        const int r = tid & 63;
        const float bdt_r = bdt[r];
        const float bph_r = bph[r];
        const float eA_r  = __expf(Areal[r]);
        const float Ai_r  = Aimag[r];
        __half* Ap = smh + APOFF / 2;

        #pragma unroll
        for (int i = 0; i < 16; i++) {
            int idx  = tid + i * 256;
            int row  = idx >> 6;
            int grow = m0 + row;

            float zdt   = P[row * LDP + r] + bdt_r;
            float dt    = (zdt > 15.f) ? zdt : __logf(1.f + __expf(zdt));
            float zph   = P[row * LDP + 64 + r] + bph_r;
            float e2z   = __expf(2.f * zph);
            float th    = 1.f - __fdividef(2.f, 1.f + e2z);
            float phase = th * PI_F;
            float decay = __expf(-dt * eA_r);
            float angle = fmaf(dt, Ai_r, phase);
            float Bv    = P[row * LDP + 128 + r];

            float sn = __sinf(angle);
            float cs = __cosf(angle);

            float a_ = sre[(size_t)grow * RANK + r];
            float b_ = sim_[(size_t)grow * RANK + r];

            float vre = fmaf(a_ * cs - b_ * sn, decay, Bv);
            nre[(size_t)grow * RANK + r] = vre;
            nim[(size_t)grow * RANK + r] = (a_ * sn + b_ * cs) * decay;
            Ap[row * LDOH + r] = __float2half(vre);
        }
    }
    __syncthreads();

    // ================= phase C: out = A' @ WC^T =================
    uint32_t aLm2[2];
    #pragma unroll
    for (int mt = 0; mt < 2; mt++) {
        int row  = wm * 32 + mt * 16 + (part & 1) * 8 + rA;
        int colh = (part >> 1) * 8;
        aLm2[mt] = sbase + APOFF + (uint32_t)(row * LDOH + colh) * 2;
    }
    uint32_t bLm2[2];
    #pragma unroll
    for (int p = 0; p < 2; p++) {
        int row = wn * 32 + p * 16 + hi8 + rA;
        bLm2[p] = sbase + B0OFF + (uint32_t)(row * LDOH + col8) * 2;
    }

    auto cpWC = [&](int t128, int b3) {
        const uint32_t so = (uint32_t)B0OFF + (uint32_t)b3 * OB_BUF;
        #pragma unroll
        for (int i = 0; i < 4; i++) {
            int c = tid + i * 256;
            int row = c >> 3, ch = c & 7;
            cp16(sbase + so + (uint32_t)(row * LDOH + ch * 8) * 2,
                 d_WCh + ((size_t)t128 * 128 + row) * RANK + ch * 8);
        }
        CP_COMMIT();
    };

    cpWC(0, 0);
    cpWC(1, 1);
    CP_WAIT1();
    __syncthreads();

    int c3 = 0;
    for (int t128 = 0; t128 < 16; ++t128) {
        float acc2[2][4][4];
        #pragma unroll
        for (int i = 0; i < 2; i++)
            #pragma unroll
            for (int j = 0; j < 4; j++)
                #pragma unroll
                for (int k = 0; k < 4; k++) acc2[i][j][k] = 0.f;

        const uint32_t so = (uint32_t)c3 * OB_BUF;
        #pragma unroll
        for (int k16 = 0; k16 < 4; k16++) {
            const uint32_t kB = (uint32_t)k16 * 32;
            uint32_t afr[2][4], bfr[2][4];
            #pragma unroll
            for (int mt = 0; mt < 2; mt++) ldsm_x4(afr[mt], aLm2[mt] + kB);
            #pragma unroll
            for (int p = 0; p < 2; p++)  ldsm_x4(bfr[p], bLm2[p] + so + kB);
            #pragma unroll
            for (int mt = 0; mt < 2; mt++)
                #pragma unroll
                for (int nt = 0; nt < 4; nt++)
                    mma_f16(acc2[mt][nt], afr[mt], &bfr[nt >> 1][(nt & 1) * 2]);
        }

        const int n0 = t128 * 128;
        #pragma unroll
        for (int mt = 0; mt < 2; mt++) {
            int row = m0 + wm * 32 + mt * 16 + g;
            #pragma unroll
            for (int nt = 0; nt < 4; nt++) {
                int col = n0 + wn * 32 + nt * 8 + 2 * t;
                *reinterpret_cast<float2*>(out + (size_t)row * DMODEL + col) =
                    make_float2(acc2[mt][nt][0], acc2[mt][nt][1]);
                *reinterpret_cast<float2*>(out + (size_t)(row + 8) * DMODEL + col) =
                    make_float2(acc2[mt][nt][2], acc2[mt][nt][3]);
            }
        }

        if (t128 + 2 < 16) {
            int nxt = c3 + 2; if (nxt >= 3) nxt -= 3;
            cpWC(t128 + 2, nxt);
            CP_WAIT1();
            __syncthreads();
        } else if (t128 + 1 < 16) {
            CP_WAIT0();
            __syncthreads();
        }
        c3 = (c3 + 1 == 3) ? 0 : c3 + 1;
    }
}

// ---------------------------------------------------------------------------
// launch
// ---------------------------------------------------------------------------
extern "C" void kernel_launch(void* const* d_in, const int* in_sizes, int n_in,
                              void* d_out, int out_size)
{
    const float* x    = (const float*)d_in[0];
    const float* sre  = (const float*)d_in[1];
    const float* sim_ = (const float*)d_in[2];
    const float* Wdt  = (const float*)d_in[3];
    const float* bdt  = (const float*)d_in[4];
    const float* Wph  = (const float*)d_in[5];
    const float* bph  = (const float*)d_in[6];
    const float* WB   = (const float*)d_in[7];
    const float* WC   = (const float*)d_in[8];
    const float* Ar   = (const float*)d_in[9];
    const float* Ai   = (const float*)d_in[10];

    float* out = (float*)d_out;
    float* nre = out + (size_t)BATCH * DMODEL;
    float* nim = nre + (size_t)BATCH * RANK;

    cudaFuncSetAttribute(fused_kernel, cudaFuncAttributeMaxDynamicSharedMemorySize, SMEM1);

    convert_weights<<<512, 256>>>(Wdt, Wph, WB, WC);
    fused_kernel<<<BATCH / 64, 256, SMEM1>>>(x, sre, sim_, bdt, bph, Ar, Ai,
                                             out, nre, nim);
}